// round 3
// baseline (speedup 1.0000x reference)
#include <cuda_runtime.h>
#include <cstdint>

#define Hdim 512
#define Ddim 64
#define Mrows 32
#define NT 256
#define S 36                      // SMEM row stride (floats): 144B, 16B-aligned
#define BMAX 65536

// ---- device scratch (no cudaMalloc allowed) ----
static __device__ float g_WzT[3][Hdim * Hdim];   // Wz1..3 transposed [k][h]
static __device__ float g_WzT0[Ddim * Hdim];     // Wz0 transposed [d][h]
static __device__ float g_WxT[3][Ddim * Hdim];   // Wx0..2 transposed [d][h]
static __device__ float g_s[3][(size_t)BMAX * Hdim];  // sigmoid(pre1..pre3)

// ---------------------------------------------------------------------------
__global__ void prep_kernel(
    const float* __restrict__ Wz0, const float* __restrict__ Wz1,
    const float* __restrict__ Wz2, const float* __restrict__ Wz3,
    const float* __restrict__ Wx0, const float* __restrict__ Wx1,
    const float* __restrict__ Wx2)
{
    for (int i = blockIdx.x * blockDim.x + threadIdx.x; i < Hdim * Hdim;
         i += gridDim.x * blockDim.x) {
        int k = i >> 9;
        int h = i & (Hdim - 1);
        g_WzT[0][i] = Wz1[h * Hdim + k];
        g_WzT[1][i] = Wz2[h * Hdim + k];
        g_WzT[2][i] = Wz3[h * Hdim + k];
        if (i < Ddim * Hdim) {
            int d = i >> 9;
            g_WzT0[i]   = Wz0[h * Ddim + d];
            g_WxT[0][i] = Wx0[h * Ddim + d];
            g_WxT[1][i] = Wx1[h * Ddim + d];
            g_WxT[2][i] = Wx2[h * Ddim + d];
        }
    }
}

// ---------------------------------------------------------------------------
// f32x2 packed-FMA helpers (FFMA2 — only reachable via PTX fma.rn.f32x2)
// ---------------------------------------------------------------------------
__device__ __forceinline__ void ffma2(uint64_t& acc, uint64_t a, uint64_t b)
{
    asm("fma.rn.f32x2 %0, %1, %2, %0;" : "+l"(acc) : "l"(a), "l"(b));
}
__device__ __forceinline__ uint64_t pk(float x, float y)
{
    uint64_t r; asm("mov.b64 %0, {%1, %2};" : "=l"(r) : "f"(x), "f"(y)); return r;
}
__device__ __forceinline__ uint64_t dup(float x)
{
    uint64_t r; asm("mov.b64 %0, {%1, %1};" : "=l"(r) : "f"(x)); return r;
}
__device__ __forceinline__ void upk(uint64_t v, float& x, float& y)
{
    asm("mov.b64 {%0, %1}, %2;" : "=f"(x), "=f"(y) : "l"(v));
}

// stable softplus + sigmoid
__device__ __forceinline__ void act(float p, float& z, float& s)
{
    float e = __expf(-fabsf(p));
    float r = 1.0f / (1.0f + e);
    z = fmaxf(p, 0.0f) + log1pf(e);
    s = (p >= 0.0f) ? r : e * r;
}

// ---------------------------------------------------------------------------
// 8x8 register-blocked GEMM core with packed f32x2 accumulation.
// acc[m*4+np] = f32x2 pair over cols (n0+2np, n0+2np+1), rows m0+m.
// WT: [K][512] row-major global. zT: SMEM [K][S].
// ---------------------------------------------------------------------------
template <int K>
__device__ __forceinline__ void gemm8x8(
    const float* __restrict__ WT, const float* zT, int n0, int m0,
    uint64_t* acc)
{
    #pragma unroll 4
    for (int k = 0; k < K; k++) {
        float4 w0 = __ldg((const float4*)(WT + (size_t)k * Hdim + n0));
        float4 w1 = __ldg((const float4*)(WT + (size_t)k * Hdim + n0 + 4));
        uint64_t b0 = pk(w0.x, w0.y), b1 = pk(w0.z, w0.w);
        uint64_t b2 = pk(w1.x, w1.y), b3 = pk(w1.z, w1.w);
        float4 a0 = *(const float4*)(zT + k * S + m0);
        float4 a1 = *(const float4*)(zT + k * S + m0 + 4);
        float av[8] = { a0.x, a0.y, a0.z, a0.w, a1.x, a1.y, a1.z, a1.w };
        #pragma unroll
        for (int m = 0; m < 8; m++) {
            uint64_t ad = dup(av[m]);
            ffma2(acc[m * 4 + 0], ad, b0);
            ffma2(acc[m * 4 + 1], ad, b1);
            ffma2(acc[m * 4 + 2], ad, b2);
            ffma2(acc[m * 4 + 3], ad, b3);
        }
    }
}

// grad[m][d] += sum_h W[h][d] * dT[h][m]   (W: [512][64] row-major)
// thread covers d-pair dp=(t&31)*2, rows mg..mg+3, mg=(t>>5)*4.
// gacc: 4 f32x2 pairs over (dp, dp+1) for 4 rows.
__device__ __forceinline__ void gmatvec(
    const float* __restrict__ W, const float* dT, int t, uint64_t* gacc)
{
    const int dp = (t & 31) * 2;
    const int mg = (t >> 5) * 4;
    #pragma unroll 4
    for (int h = 0; h < Hdim; h++) {
        float2 w   = __ldg((const float2*)(W + h * Ddim + dp));
        float2 a01 = *(const float2*)(dT + h * S + mg);
        float2 a23 = *(const float2*)(dT + h * S + mg + 2);
        uint64_t wp = pk(w.x, w.y);
        ffma2(gacc[0], dup(a01.x), wp);
        ffma2(gacc[1], dup(a01.y), wp);
        ffma2(gacc[2], dup(a23.x), wp);
        ffma2(gacc[3], dup(a23.y), wp);
    }
}

// ---------------------------------------------------------------------------
// Fused ICNN forward + backward, 32 samples / CTA, 8x8 thread tiles.
// ---------------------------------------------------------------------------
__global__ void __launch_bounds__(NT, 1) icnn_kernel(
    const float* __restrict__ state,
    const float* __restrict__ bz0,
    const float* __restrict__ bx0,
    const float* __restrict__ bx1,
    const float* __restrict__ bx2,
    const float* __restrict__ WzL,
    const float* __restrict__ WxL,
    const float* __restrict__ Wz0,
    const float* __restrict__ Wz1,
    const float* __restrict__ Wz2,
    const float* __restrict__ Wz3,
    const float* __restrict__ Wx0,
    const float* __restrict__ Wx1,
    const float* __restrict__ Wx2,
    float* __restrict__ out)
{
    extern __shared__ float smem[];
    float* bufA = smem;                       // [512][S]
    float* bufB = smem + Hdim * S;            // [512][S]
    float* xT   = smem + 2 * Hdim * S;        // [64][S]

    const int t = threadIdx.x;
    const int tcol = t & 63;                  // warp-contiguous -> coalesced LDG
    const int trow = t >> 6;                  // constant within a warp -> LDS broadcast
    const int n0 = tcol << 3;
    const int m0 = trow << 3;
    const int rowbase = blockIdx.x * Mrows;

    // load x tile (x = state - 1), transposed [d][m]
    #pragma unroll
    for (int i = 0; i < (Mrows * Ddim) / NT; i++) {
        int idx = t + i * NT;
        int m = idx >> 6;
        int d = idx & 63;
        xT[d * S + m] = state[(size_t)(rowbase + m) * Ddim + d] - 1.0f;
    }
    __syncthreads();

    uint64_t acc[32];

    // ---------------- Layer 1: pre1 = Wz0 x + bz0 ----------------
    #pragma unroll
    for (int i = 0; i < 32; i++) acc[i] = 0ull;
    gemm8x8<Ddim>(g_WzT0, xT, n0, m0, acc);
    {
        float4 bb0 = __ldg((const float4*)(bz0 + n0));
        float4 bb1 = __ldg((const float4*)(bz0 + n0 + 4));
        float bn[8] = { bb0.x, bb0.y, bb0.z, bb0.w, bb1.x, bb1.y, bb1.z, bb1.w };
        #pragma unroll
        for (int m = 0; m < 8; m++) {
            float z[8], sg[8];
            #pragma unroll
            for (int np = 0; np < 4; np++) {
                float p0, p1; upk(acc[m * 4 + np], p0, p1);
                act(p0 + bn[2 * np],     z[2 * np],     sg[2 * np]);
                act(p1 + bn[2 * np + 1], z[2 * np + 1], sg[2 * np + 1]);
            }
            int mm = m0 + m;
            #pragma unroll
            for (int j = 0; j < 8; j++) {         // rotate to spread banks
                int jj = (j + tcol) & 7;
                bufA[(n0 + jj) * S + mm] = z[jj];
            }
            size_t base = (size_t)(rowbase + mm) * Hdim + n0;
            *(float4*)(g_s[0] + base)     = make_float4(sg[0], sg[1], sg[2], sg[3]);
            *(float4*)(g_s[0] + base + 4) = make_float4(sg[4], sg[5], sg[6], sg[7]);
        }
    }
    __syncthreads();

    // ---------------- Layers 2..4 ----------------
    {
        float* bufs[2] = { bufA, bufB };
        #pragma unroll 1
        for (int l = 0; l < 3; l++) {
            const float* WzTl = (l == 0) ? g_WzT[0] : (l == 1) ? g_WzT[1] : g_WzT[2];
            const float* WxTl = (l == 0) ? g_WxT[0] : (l == 1) ? g_WxT[1] : g_WxT[2];
            const float* bl   = (l == 0) ? bx0 : (l == 1) ? bx1 : bx2;
            const float* src = bufs[l & 1];
            float* dst = bufs[(l & 1) ^ 1];
            #pragma unroll
            for (int i = 0; i < 32; i++) acc[i] = 0ull;
            gemm8x8<Hdim>(WzTl, src, n0, m0, acc);
            gemm8x8<Ddim>(WxTl, xT,  n0, m0, acc);

            float4 bb0 = __ldg((const float4*)(bl + n0));
            float4 bb1 = __ldg((const float4*)(bl + n0 + 4));
            float bn[8] = { bb0.x, bb0.y, bb0.z, bb0.w, bb1.x, bb1.y, bb1.z, bb1.w };

            if (l < 2) {
                float* sdst = g_s[l + 1];
                #pragma unroll
                for (int m = 0; m < 8; m++) {
                    float z[8], sg[8];
                    #pragma unroll
                    for (int np = 0; np < 4; np++) {
                        float p0, p1; upk(acc[m * 4 + np], p0, p1);
                        act(p0 + bn[2 * np],     z[2 * np],     sg[2 * np]);
                        act(p1 + bn[2 * np + 1], z[2 * np + 1], sg[2 * np + 1]);
                    }
                    int mm = m0 + m;
                    #pragma unroll
                    for (int j = 0; j < 8; j++) {
                        int jj = (j + tcol) & 7;
                        dst[(n0 + jj) * S + mm] = z[jj];
                    }
                    size_t base = (size_t)(rowbase + mm) * Hdim + n0;
                    *(float4*)(sdst + base)     = make_float4(sg[0], sg[1], sg[2], sg[3]);
                    *(float4*)(sdst + base + 4) = make_float4(sg[4], sg[5], sg[6], sg[7]);
                }
            } else {
                // layer 4: d4T[n][m] = WzL[n] * sigmoid(pre4)
                float4 wl0 = __ldg((const float4*)(WzL + n0));
                float4 wl1 = __ldg((const float4*)(WzL + n0 + 4));
                float wl[8] = { wl0.x, wl0.y, wl0.z, wl0.w, wl1.x, wl1.y, wl1.z, wl1.w };
                #pragma unroll
                for (int m = 0; m < 8; m++) {
                    float dv[8];
                    #pragma unroll
                    for (int np = 0; np < 4; np++) {
                        float p0, p1; upk(acc[m * 4 + np], p0, p1);
                        float zt, s0, s1;
                        act(p0 + bn[2 * np],     zt, s0);
                        act(p1 + bn[2 * np + 1], zt, s1);
                        dv[2 * np]     = wl[2 * np] * s0;
                        dv[2 * np + 1] = wl[2 * np + 1] * s1;
                    }
                    int mm = m0 + m;
                    #pragma unroll
                    for (int j = 0; j < 8; j++) {
                        int jj = (j + tcol) & 7;
                        dst[(n0 + jj) * S + mm] = dv[jj];
                    }
                }
            }
            __syncthreads();
        }
    }

    // ---------------- Backward ----------------
    uint64_t gacc[4];
    #pragma unroll
    for (int i = 0; i < 4; i++) gacc[i] = 0ull;
    {
        float* bufs[2] = { bufB, bufA };       // d4T sits in bufB
        #pragma unroll 1
        for (int j = 0; j < 3; j++) {
            const float* WzB = (j == 0) ? Wz3 : (j == 1) ? Wz2 : Wz1;
            const float* WxG = (j == 0) ? Wx2 : (j == 1) ? Wx1 : Wx0;
            const float* ssrc = g_s[2 - j];
            const float* src = bufs[j & 1];
            float* dst = bufs[(j & 1) ^ 1];

            gmatvec(WxG, src, t, gacc);        // grad += Wx^T d

            #pragma unroll
            for (int i = 0; i < 32; i++) acc[i] = 0ull;
            gemm8x8<Hdim>(WzB, src, n0, m0, acc);   // t = Wz^T d (orig layout = transposed-apply)

            #pragma unroll
            for (int m = 0; m < 8; m++) {
                int mm = m0 + m;
                size_t base = (size_t)(rowbase + mm) * Hdim + n0;
                float4 s0 = __ldg((const float4*)(ssrc + base));
                float4 s1 = __ldg((const float4*)(ssrc + base + 4));
                float sv[8] = { s0.x, s0.y, s0.z, s0.w, s1.x, s1.y, s1.z, s1.w };
                float dv[8];
                #pragma unroll
                for (int np = 0; np < 4; np++) {
                    float p0, p1; upk(acc[m * 4 + np], p0, p1);
                    dv[2 * np]     = sv[2 * np] * p0;
                    dv[2 * np + 1] = sv[2 * np + 1] * p1;
                }
                #pragma unroll
                for (int jj0 = 0; jj0 < 8; jj0++) {
                    int jj = (jj0 + tcol) & 7;
                    dst[(n0 + jj) * S + mm] = dv[jj];
                }
            }
            __syncthreads();
        }
        gmatvec(Wz0, bufA, t, gacc);           // grad += Wz0^T d1 (d1T in bufA)
    }

    // ---------------- Output: grad + WxL ----------------
    {
        const int dp = (t & 31) * 2;
        const int mg = (t >> 5) * 4;
        float2 wxl = __ldg((const float2*)(WxL + dp));
        #pragma unroll
        for (int i = 0; i < 4; i++) {
            float g0, g1; upk(gacc[i], g0, g1);
            float2 r; r.x = g0 + wxl.x; r.y = g1 + wxl.y;
            *(float2*)(out + (size_t)(rowbase + mg + i) * Ddim + dp) = r;
        }
    }
}

// ---------------------------------------------------------------------------
extern "C" void kernel_launch(void* const* d_in, const int* in_sizes, int n_in,
                              void* d_out, int out_size)
{
    const float* state = (const float*)d_in[0];
    const float* Wz0   = (const float*)d_in[1];
    const float* bz0   = (const float*)d_in[2];
    const float* Wz1   = (const float*)d_in[3];
    const float* Wz2   = (const float*)d_in[4];
    const float* Wz3   = (const float*)d_in[5];
    const float* WzL   = (const float*)d_in[6];
    const float* Wx0   = (const float*)d_in[7];
    const float* bx0   = (const float*)d_in[8];
    const float* Wx1   = (const float*)d_in[9];
    const float* bx1   = (const float*)d_in[10];
    const float* Wx2   = (const float*)d_in[11];
    const float* bx2   = (const float*)d_in[12];
    const float* WxL   = (const float*)d_in[13];
    float* out = (float*)d_out;

    int B = in_sizes[0] / Ddim;
    int smem_bytes = (2 * Hdim + Ddim) * S * (int)sizeof(float);  // ~153 KB

    cudaFuncSetAttribute(icnn_kernel, cudaFuncAttributeMaxDynamicSharedMemorySize,
                         smem_bytes);

    prep_kernel<<<256, 256>>>(Wz0, Wz1, Wz2, Wz3, Wx0, Wx1, Wx2);
    icnn_kernel<<<B / Mrows, NT, smem_bytes>>>(
        state, bz0, bx0, bx1, bx2, WzL, WxL,
        Wz0, Wz1, Wz2, Wz3, Wx0, Wx1, Wx2, out);
}

// round 5
// speedup vs baseline: 2.2365x; 2.2365x over previous
#include <cuda_runtime.h>
#include <cuda_bf16.h>
#include <cstdint>

#define Bsz 65536
#define Hd 512
#define Dd 64
typedef __nv_bfloat16 bf;

// ---- static device scratch (no cudaMalloc allowed) ----
static __device__ __align__(16) bf g_Wz_h[3][Hd * Hd],  g_Wz_l[3][Hd * Hd];   // fwd [n][k]
static __device__ __align__(16) bf g_WzT_h[3][Hd * Hd], g_WzT_l[3][Hd * Hd];  // bwd [n][k]=W[k][n]
static __device__ __align__(16) bf g_Wz0_h[Hd * Dd],    g_Wz0_l[Hd * Dd];     // [512][64]
static __device__ __align__(16) bf g_Wx_h[3][Hd * Dd],  g_Wx_l[3][Hd * Dd];   // [512][64]
static __device__ __align__(16) bf g_GT_h[4][Dd * Hd],  g_GT_l[4][Dd * Hd];   // grad B [64][512]
static __device__ __align__(16) bf g_x_h[(size_t)Bsz * Dd],  g_x_l[(size_t)Bsz * Dd];
static __device__ __align__(16) bf g_zA_h[(size_t)Bsz * Hd], g_zA_l[(size_t)Bsz * Hd];
static __device__ __align__(16) bf g_zB_h[(size_t)Bsz * Hd], g_zB_l[(size_t)Bsz * Hd];
static __device__ __align__(16) bf g_s_h[3][(size_t)Bsz * Hd], g_s_l[3][(size_t)Bsz * Hd];

struct PassArgs {
    const bf *Ah[4], *Al[4], *Bh[4], *Bl[4];
    int K[4]; int nseg; int mode;       // 0 fwd, 1 last, 2 bwd, 3 grad
    const float *bias, *aux;
    const bf *sh, *sl;                  // elementwise sigmoid (mode 2)
    bf *oh, *ol, *osh, *osl;            // outputs (z planes, s planes)
    float* ofp;                         // fp32 out (mode 3)
};
static __device__ PassArgs g_pass[8];

// ---- PTX helpers ----
__device__ __forceinline__ uint32_t smem_u32(const void* p) {
    uint32_t a;
    asm("{ .reg .u64 t; cvta.to.shared.u64 t, %1; cvt.u32.u64 %0, t; }" : "=r"(a) : "l"(p));
    return a;
}
__device__ __forceinline__ void cpa16(uint32_t dst, const void* src) {
    asm volatile("cp.async.cg.shared.global [%0], [%1], 16;" :: "r"(dst), "l"(src));
}
#define CP_COMMIT() asm volatile("cp.async.commit_group;" ::: "memory")
#define CP_WAIT1()  asm volatile("cp.async.wait_group 1;" ::: "memory")
#define CP_WAIT0()  asm volatile("cp.async.wait_group 0;" ::: "memory")
#define LDSM4(R, addr) \
    asm volatile("ldmatrix.sync.aligned.m8n8.x4.shared.b16 {%0,%1,%2,%3}, [%4];" \
        : "=r"((R)[0]), "=r"((R)[1]), "=r"((R)[2]), "=r"((R)[3]) : "r"(addr))
#define MMA16816(c, A, b0, b1) \
    asm volatile("mma.sync.aligned.m16n8k16.row.col.f32.bf16.bf16.f32 " \
        "{%0,%1,%2,%3}, {%4,%5,%6,%7}, {%8,%9}, {%0,%1,%2,%3};" \
        : "+f"((c)[0]), "+f"((c)[1]), "+f"((c)[2]), "+f"((c)[3]) \
        : "r"((A)[0]), "r"((A)[1]), "r"((A)[2]), "r"((A)[3]), "r"(b0), "r"(b1))

__device__ __forceinline__ void act(float p, float& z, float& s) {
    float e = __expf(-fabsf(p));
    float r = 1.0f / (1.0f + e);
    z = fmaxf(p, 0.0f) + log1pf(e);
    s = (p >= 0.0f) ? r : e * r;
}
__device__ __forceinline__ void bsplit(float v, bf& h, bf& l) {
    h = __float2bfloat16(v);
    l = __float2bfloat16(v - __bfloat162float(h));
}
__device__ __forceinline__ uint32_t pk2(bf a, bf b) {
    __nv_bfloat162 t(a, b);
    return *reinterpret_cast<uint32_t*>(&t);
}
// store (v0,v1) split hi/lo at planes +off
__device__ __forceinline__ void st_split(bf* ph, bf* pl, size_t off, float v0, float v1) {
    bf h0, l0, h1, l1;
    bsplit(v0, h0, l0); bsplit(v1, h1, l1);
    *reinterpret_cast<uint32_t*>(ph + off) = pk2(h0, h1);
    *reinterpret_cast<uint32_t*>(pl + off) = pk2(l0, l1);
}
// smem swizzled offset: row (64B each), jb = 16B unit 0..3
__device__ __forceinline__ uint32_t swz(int r, int jb) {
    return (uint32_t)((r << 6) + ((jb ^ ((r >> 1) & 3)) << 4));
}

// ---- prep kernels ----
__global__ void prep_w(const float* __restrict__ Wz0, const float* __restrict__ Wz1,
                       const float* __restrict__ Wz2, const float* __restrict__ Wz3,
                       const float* __restrict__ Wx0, const float* __restrict__ Wx1,
                       const float* __restrict__ Wx2)
{
    const float* Wz[3] = { Wz1, Wz2, Wz3 };
    const float* Wx[3] = { Wx0, Wx1, Wx2 };
    for (int i = blockIdx.x * blockDim.x + threadIdx.x; i < Hd * Hd;
         i += gridDim.x * blockDim.x) {
        int n = i >> 9, k = i & 511;
        #pragma unroll
        for (int l = 0; l < 3; l++) {
            bf h, lo; bsplit(Wz[l][i], h, lo);
            g_Wz_h[l][i] = h; g_Wz_l[l][i] = lo;
            g_WzT_h[l][k * Hd + n] = h; g_WzT_l[l][k * Hd + n] = lo;
        }
        if (i < Hd * Dd) {
            int n2 = i >> 6, d = i & 63;
            bf h, lo; bsplit(Wz0[i], h, lo);
            g_Wz0_h[i] = h; g_Wz0_l[i] = lo;
            g_GT_h[0][d * Hd + n2] = h; g_GT_l[0][d * Hd + n2] = lo;
            #pragma unroll
            for (int l = 0; l < 3; l++) {
                bsplit(Wx[l][i], h, lo);
                g_Wx_h[l][i] = h; g_Wx_l[l][i] = lo;
                g_GT_h[l + 1][d * Hd + n2] = h; g_GT_l[l + 1][d * Hd + n2] = lo;
            }
        }
    }
}

__global__ void prep_x(const float* __restrict__ state)
{
    for (size_t i = blockIdx.x * blockDim.x + threadIdx.x; i < (size_t)Bsz * Dd;
         i += (size_t)gridDim.x * blockDim.x) {
        bf h, l; bsplit(state[i] - 1.0f, h, l);
        g_x_h[i] = h; g_x_l[i] = l;
    }
}

__global__ void init_args(const float* bz0, const float* bx0, const float* bx1,
                          const float* bx2, const float* WzL, const float* WxL,
                          float* out)
{
    if (threadIdx.x != 0 || blockIdx.x != 0) return;
    auto set = [] (int p, int nseg, int mode, const float* bias, const float* aux,
                   const bf* sh, const bf* sl, bf* oh, bf* ol, bf* osh, bf* osl, float* ofp) {
        PassArgs& a = g_pass[p];
        a.nseg = nseg; a.mode = mode; a.bias = bias; a.aux = aux;
        a.sh = sh; a.sl = sl; a.oh = oh; a.ol = ol; a.osh = osh; a.osl = osl; a.ofp = ofp;
    };
    auto seg = [] (int p, int s, const bf* Ah, const bf* Al, const bf* Bh, const bf* Bl, int K) {
        PassArgs& a = g_pass[p];
        a.Ah[s] = Ah; a.Al[s] = Al; a.Bh[s] = Bh; a.Bl[s] = Bl; a.K[s] = K;
    };
    set(0, 1, 0, bz0, 0, 0, 0, g_zA_h, g_zA_l, g_s_h[0], g_s_l[0], 0);
    seg(0, 0, g_x_h, g_x_l, g_Wz0_h, g_Wz0_l, Dd);
    set(1, 2, 0, bx0, 0, 0, 0, g_zB_h, g_zB_l, g_s_h[1], g_s_l[1], 0);
    seg(1, 0, g_zA_h, g_zA_l, g_Wz_h[0], g_Wz_l[0], Hd);
    seg(1, 1, g_x_h, g_x_l, g_Wx_h[0], g_Wx_l[0], Dd);
    set(2, 2, 0, bx1, 0, 0, 0, g_zA_h, g_zA_l, g_s_h[2], g_s_l[2], 0);
    seg(2, 0, g_zB_h, g_zB_l, g_Wz_h[1], g_Wz_l[1], Hd);
    seg(2, 1, g_x_h, g_x_l, g_Wx_h[1], g_Wx_l[1], Dd);
    set(3, 2, 1, bx2, WzL, 0, 0, g_zB_h, g_zB_l, 0, 0, 0);   // d4 -> zB planes
    seg(3, 0, g_zA_h, g_zA_l, g_Wz_h[2], g_Wz_l[2], Hd);
    seg(3, 1, g_x_h, g_x_l, g_Wx_h[2], g_Wx_l[2], Dd);
    set(4, 1, 2, 0, 0, g_s_h[2], g_s_l[2], g_s_h[2], g_s_l[2], 0, 0, 0); // d3 -> s3 planes
    seg(4, 0, g_zB_h, g_zB_l, g_WzT_h[2], g_WzT_l[2], Hd);
    set(5, 1, 2, 0, 0, g_s_h[1], g_s_l[1], g_s_h[1], g_s_l[1], 0, 0, 0); // d2 -> s2
    seg(5, 0, g_s_h[2], g_s_l[2], g_WzT_h[1], g_WzT_l[1], Hd);
    set(6, 1, 2, 0, 0, g_s_h[0], g_s_l[0], g_s_h[0], g_s_l[0], 0, 0, 0); // d1 -> s1
    seg(6, 0, g_s_h[1], g_s_l[1], g_WzT_h[0], g_WzT_l[0], Hd);
    set(7, 4, 3, 0, WxL, 0, 0, 0, 0, 0, 0, out);
    seg(7, 0, g_s_h[0], g_s_l[0], g_GT_h[0], g_GT_l[0], Hd);  // Wz0^T d1
    seg(7, 1, g_s_h[1], g_s_l[1], g_GT_h[1], g_GT_l[1], Hd);  // Wx0^T d2
    seg(7, 2, g_s_h[2], g_s_l[2], g_GT_h[2], g_GT_l[2], Hd);  // Wx1^T d3
    seg(7, 3, g_zB_h, g_zB_l, g_GT_h[3], g_GT_l[3], Hd);      // Wx2^T d4
}

// ---------------------------------------------------------------------------
// GEMM pass: CTA 128m x NTn, 256 thr (warps 4m x 2n -> warp 32m x NT/2 n),
// bf16 3-product mma.sync, 3-stage cp.async pipeline.
// ---------------------------------------------------------------------------
template <int NT>
__global__ void __launch_bounds__(256, 1) gemm_pass(int pi)
{
    extern __shared__ char smem[];
    const uint32_t smb = smem_u32(smem);
    const PassArgs& a = g_pass[pi];
    const int tid = threadIdx.x, lane = tid & 31, w = tid >> 5;
    const int warpM = w & 3, warpN = w >> 2;
    const int rowbase = blockIdx.y * 128;
    const int nb = blockIdx.x * NT;
    const int NW8 = NT / 16;               // n8 frags per warp (8 or 4)

    int startc[5]; startc[0] = 0;
    const int nseg = a.nseg;
    for (int s = 0; s < nseg; s++) startc[s + 1] = startc[s] + a.K[s] / 32;
    const int totalc = startc[nseg];

    auto stage = [&](int c, int buf) {
        int s = 0;
        while (c >= startc[s + 1]) s++;
        const int kc = (c - startc[s]) * 32;
        const int Ks = a.K[s];
        const bf *Ah = a.Ah[s], *Al = a.Al[s], *Bh = a.Bh[s], *Bl = a.Bl[s];
        const uint32_t sb = smb + buf * 32768u;
        #pragma unroll
        for (int it = 0; it < 2; it++) {
            int i = tid + it * 256;
            int r = i >> 2, jb = i & 3;
            uint32_t d = swz(r, jb);
            size_t so = (size_t)(rowbase + r) * Ks + kc + jb * 8;
            cpa16(sb + d, Ah + so);
            cpa16(sb + 8192 + d, Al + so);
        }
        #pragma unroll
        for (int it = 0; it < NT / 64; it++) {
            int i = tid + it * 256;
            int r = i >> 2, jb = i & 3;
            uint32_t d = swz(r, jb);
            size_t so = (size_t)(nb + r) * Ks + kc + jb * 8;
            cpa16(sb + 16384 + d, Bh + so);
            cpa16(sb + 24576 + d, Bl + so);
        }
        CP_COMMIT();
    };

    // per-lane ldmatrix metadata
    const int tq = lane >> 3, rq = lane & 7;
    const int mA = warpM * 32 + (tq & 1) * 8 + rq;   // + mt*16
    const int kselA = tq >> 1;
    const uint32_t moff = (uint32_t)(mA << 6);
    const int xa = (mA >> 1) & 3;
    const int nB = warpN * (NT / 2) + (tq >> 1) * 8 + rq;  // + tile*16
    const int kselB = tq & 1;
    const uint32_t noff = (uint32_t)(nB << 6);
    const int xb = (nB >> 1) & 3;

    float acc[2][8][4];
    #pragma unroll
    for (int i = 0; i < 2; i++)
        #pragma unroll
        for (int j = 0; j < 8; j++)
            #pragma unroll
            for (int cq = 0; cq < 4; cq++) acc[i][j][cq] = 0.0f;

    stage(0, 0);
    if (totalc > 1) stage(1, 1); else CP_COMMIT();

    for (int c = 0; c < totalc; c++) {
        if (c >= totalc - 2) { CP_WAIT0(); } else { CP_WAIT1(); }
        __syncthreads();
        const uint32_t sb = smb + (uint32_t)(c % 3) * 32768u;
        #pragma unroll
        for (int k16 = 0; k16 < 2; k16++) {
            uint32_t ah[2][4], al[2][4], bh[4][4], bl[4][4];
            #pragma unroll
            for (int mt = 0; mt < 2; mt++) {
                uint32_t ad = sb + moff + (uint32_t)(mt * 1024)
                            + (uint32_t)((((k16 * 2 + kselA) ^ xa)) << 4);
                LDSM4(ah[mt], ad);
                LDSM4(al[mt], ad + 8192);
            }
            #pragma unroll
            for (int ti = 0; ti < NW8 / 2; ti++) {
                uint32_t bd = sb + 16384 + noff + (uint32_t)(ti * 1024)
                            + (uint32_t)((((k16 * 2 + kselB) ^ xb)) << 4);
                LDSM4(bh[ti], bd);
                LDSM4(bl[ti], bd + 8192);
            }
            #pragma unroll
            for (int mt = 0; mt < 2; mt++)
                #pragma unroll
                for (int j = 0; j < NW8; j++) {
                    uint32_t* bhp = &bh[j >> 1][(j & 1) * 2];
                    uint32_t* blp = &bl[j >> 1][(j & 1) * 2];
                    MMA16816(acc[mt][j], ah[mt], bhp[0], bhp[1]);
                    MMA16816(acc[mt][j], al[mt], bhp[0], bhp[1]);
                    MMA16816(acc[mt][j], ah[mt], blp[0], blp[1]);
                }
        }
        if (c + 2 < totalc) stage(c + 2, (c + 2) % 3); else CP_COMMIT();
    }

    // ---- epilogue ----
    const int mode = a.mode;
    #pragma unroll
    for (int mt = 0; mt < 2; mt++)
        #pragma unroll
        for (int j = 0; j < NW8; j++) {
            float* q = acc[mt][j];
            const int m0 = rowbase + warpM * 32 + mt * 16 + (lane >> 2);
            const int np = nb + warpN * (NT / 2) + j * 8 + (lane & 3) * 2;
            #pragma unroll
            for (int half = 0; half < 2; half++) {
                const int m = m0 + half * 8;
                float v0 = q[half * 2], v1 = q[half * 2 + 1];
                if (mode == 0) {
                    float p0 = v0 + __ldg(a.bias + np), p1 = v1 + __ldg(a.bias + np + 1);
                    float z0, s0, z1, s1;
                    act(p0, z0, s0); act(p1, z1, s1);
                    size_t o = (size_t)m * Hd + np;
                    st_split(a.oh, a.ol, o, z0, z1);
                    st_split(a.osh, a.osl, o, s0, s1);
                } else if (mode == 1) {
                    float p0 = v0 + __ldg(a.bias + np), p1 = v1 + __ldg(a.bias + np + 1);
                    float zt, s0, s1;
                    act(p0, zt, s0); act(p1, zt, s1);
                    float d0 = __ldg(a.aux + np) * s0;
                    float d1 = __ldg(a.aux + np + 1) * s1;
                    st_split(a.oh, a.ol, (size_t)m * Hd + np, d0, d1);
                } else if (mode == 2) {
                    size_t o = (size_t)m * Hd + np;
                    uint32_t sh2 = *reinterpret_cast<const uint32_t*>(a.sh + o);
                    uint32_t sl2 = *reinterpret_cast<const uint32_t*>(a.sl + o);
                    __nv_bfloat162 shh = *reinterpret_cast<__nv_bfloat162*>(&sh2);
                    __nv_bfloat162 sll = *reinterpret_cast<__nv_bfloat162*>(&sl2);
                    float s0 = __bfloat162float(shh.x) + __bfloat162float(sll.x);
                    float s1 = __bfloat162float(shh.y) + __bfloat162float(sll.y);
                    st_split(a.oh, a.ol, o, s0 * v0, s1 * v1);
                } else {
                    float2 r;
                    r.x = v0 + __ldg(a.aux + np);
                    r.y = v1 + __ldg(a.aux + np + 1);
                    *reinterpret_cast<float2*>(a.ofp + (size_t)m * Dd + np) = r;
                }
            }
        }
}

// ---------------------------------------------------------------------------
extern "C" void kernel_launch(void* const* d_in, const int* in_sizes, int n_in,
                              void* d_out, int out_size)
{
    const float* state = (const float*)d_in[0];
    const float* Wz0   = (const float*)d_in[1];
    const float* bz0   = (const float*)d_in[2];
    const float* Wz1   = (const float*)d_in[3];
    const float* Wz2   = (const float*)d_in[4];
    const float* Wz3   = (const float*)d_in[5];
    const float* WzL   = (const float*)d_in[6];
    const float* Wx0   = (const float*)d_in[7];
    const float* bx0   = (const float*)d_in[8];
    const float* Wx1   = (const float*)d_in[9];
    const float* bx1   = (const float*)d_in[10];
    const float* Wx2   = (const float*)d_in[11];
    const float* bx2   = (const float*)d_in[12];
    const float* WxL   = (const float*)d_in[13];
    float* out = (float*)d_out;

    const int smem_bytes = 3 * 32768;   // 96 KB
    cudaFuncSetAttribute(gemm_pass<128>, cudaFuncAttributeMaxDynamicSharedMemorySize, smem_bytes);
    cudaFuncSetAttribute(gemm_pass<64>,  cudaFuncAttributeMaxDynamicSharedMemorySize, smem_bytes);

    prep_w<<<512, 256>>>(Wz0, Wz1, Wz2, Wz3, Wx0, Wx1, Wx2);
    prep_x<<<512, 256>>>(state);
    init_args<<<1, 32>>>(bz0, bx0, bx1, bx2, WzL, WxL, out);

    dim3 g128(Hd / 128, Bsz / 128);   // (4, 512)
    dim3 g64(1, Bsz / 128);           // (1, 512)
    for (int p = 0; p < 7; p++)
        gemm_pass<128><<<g128, 256, smem_bytes>>>(p);
    gemm_pass<64><<<g64, 256, smem_bytes>>>(7);
}

// round 6
// speedup vs baseline: 3.3990x; 1.5198x over previous
#include <cuda_runtime.h>
#include <cuda_bf16.h>
#include <cstdint>

#define Bsz 65536
#define Hd 512
#define Dd 64
typedef __nv_bfloat16 bf;

// ---- static device scratch (no cudaMalloc allowed) ----
static __device__ __align__(16) bf g_Wz_h[3][Hd * Hd],  g_Wz_l[3][Hd * Hd];   // fwd [n][k]
static __device__ __align__(16) bf g_WzT_h[3][Hd * Hd], g_WzT_l[3][Hd * Hd];  // bwd [n][k]
static __device__ __align__(16) bf g_Wz0_h[Hd * Dd],    g_Wz0_l[Hd * Dd];
static __device__ __align__(16) bf g_Wx_h[3][Hd * Dd],  g_Wx_l[3][Hd * Dd];
static __device__ __align__(16) bf g_GT_h[4][Dd * Hd],  g_GT_l[4][Dd * Hd];   // grad B [64][512]
static __device__ __align__(16) bf g_x_h[(size_t)Bsz * Dd],  g_x_l[(size_t)Bsz * Dd];
static __device__ __align__(16) bf g_z_h[3][(size_t)Bsz * Hd], g_z_l[3][(size_t)Bsz * Hd];
static __device__ __align__(16) bf g_d4_h[(size_t)Bsz * Hd], g_d4_l[(size_t)Bsz * Hd];

struct PassArgs {
    const bf *Ah[4], *Al[4], *Bh[4], *Bl[4];
    int K[4]; int nseg; int mode;       // 0 fwd, 1 last, 2 bwd, 3 grad
    const float *bias, *aux;
    const bf *sh, *sl;                  // z planes for sigmoid recompute (mode 2)
    bf *oh, *ol;                        // bf16 hi/lo output planes
    float* ofp;                         // fp32 out (mode 3)
};
static __device__ PassArgs g_pass[8];

// ---- PTX helpers ----
__device__ __forceinline__ uint32_t smem_u32(const void* p) {
    uint32_t a;
    asm("{ .reg .u64 t; cvta.to.shared.u64 t, %1; cvt.u32.u64 %0, t; }" : "=r"(a) : "l"(p));
    return a;
}
__device__ __forceinline__ void cpa16(uint32_t dst, const void* src) {
    asm volatile("cp.async.cg.shared.global [%0], [%1], 16;" :: "r"(dst), "l"(src));
}
#define CP_COMMIT() asm volatile("cp.async.commit_group;" ::: "memory")
#define CP_WAIT1()  asm volatile("cp.async.wait_group 1;" ::: "memory")
#define CP_WAIT0()  asm volatile("cp.async.wait_group 0;" ::: "memory")
#define LDSM4(R, addr) \
    asm volatile("ldmatrix.sync.aligned.m8n8.x4.shared.b16 {%0,%1,%2,%3}, [%4];" \
        : "=r"((R)[0]), "=r"((R)[1]), "=r"((R)[2]), "=r"((R)[3]) : "r"(addr))
#define MMA16816(c, A, b0, b1) \
    asm volatile("mma.sync.aligned.m16n8k16.row.col.f32.bf16.bf16.f32 " \
        "{%0,%1,%2,%3}, {%4,%5,%6,%7}, {%8,%9}, {%0,%1,%2,%3};" \
        : "+f"((c)[0]), "+f"((c)[1]), "+f"((c)[2]), "+f"((c)[3]) \
        : "r"((A)[0]), "r"((A)[1]), "r"((A)[2]), "r"((A)[3]), "r"(b0), "r"(b1))

__device__ __forceinline__ void act(float p, float& z, float& s) {
    float e = __expf(-fabsf(p));
    float r = 1.0f / (1.0f + e);
    z = fmaxf(p, 0.0f) + log1pf(e);
    s = (p >= 0.0f) ? r : e * r;
}
__device__ __forceinline__ void bsplit(float v, bf& h, bf& l) {
    h = __float2bfloat16(v);
    l = __float2bfloat16(v - __bfloat162float(h));
}
__device__ __forceinline__ uint32_t pk2(bf a, bf b) {
    __nv_bfloat162 t(a, b);
    return *reinterpret_cast<uint32_t*>(&t);
}
__device__ __forceinline__ void st_split(bf* ph, bf* pl, size_t off, float v0, float v1) {
    bf h0, l0, h1, l1;
    bsplit(v0, h0, l0); bsplit(v1, h1, l1);
    *reinterpret_cast<uint32_t*>(ph + off) = pk2(h0, h1);
    *reinterpret_cast<uint32_t*>(pl + off) = pk2(l0, l1);
}
__device__ __forceinline__ uint32_t swz(int r, int jb) {
    return (uint32_t)((r << 6) + ((jb ^ ((r >> 1) & 3)) << 4));
}

// ---- prep kernels ----
__global__ void prep_w(const float* __restrict__ Wz0, const float* __restrict__ Wz1,
                       const float* __restrict__ Wz2, const float* __restrict__ Wz3,
                       const float* __restrict__ Wx0, const float* __restrict__ Wx1,
                       const float* __restrict__ Wx2)
{
    const float* Wz[3] = { Wz1, Wz2, Wz3 };
    const float* Wx[3] = { Wx0, Wx1, Wx2 };
    for (int i = blockIdx.x * blockDim.x + threadIdx.x; i < Hd * Hd;
         i += gridDim.x * blockDim.x) {
        int n = i >> 9, k = i & 511;
        #pragma unroll
        for (int l = 0; l < 3; l++) {
            bf h, lo; bsplit(Wz[l][i], h, lo);
            g_Wz_h[l][i] = h; g_Wz_l[l][i] = lo;
            g_WzT_h[l][k * Hd + n] = h; g_WzT_l[l][k * Hd + n] = lo;
        }
        if (i < Hd * Dd) {
            int n2 = i >> 6, d = i & 63;
            bf h, lo; bsplit(Wz0[i], h, lo);
            g_Wz0_h[i] = h; g_Wz0_l[i] = lo;
            g_GT_h[0][d * Hd + n2] = h; g_GT_l[0][d * Hd + n2] = lo;
            #pragma unroll
            for (int l = 0; l < 3; l++) {
                bsplit(Wx[l][i], h, lo);
                g_Wx_h[l][i] = h; g_Wx_l[l][i] = lo;
                g_GT_h[l + 1][d * Hd + n2] = h; g_GT_l[l + 1][d * Hd + n2] = lo;
            }
        }
    }
}

__global__ void prep_x(const float* __restrict__ state)
{
    for (size_t i = blockIdx.x * blockDim.x + threadIdx.x; i < (size_t)Bsz * Dd;
         i += (size_t)gridDim.x * blockDim.x) {
        bf h, l; bsplit(state[i] - 1.0f, h, l);
        g_x_h[i] = h; g_x_l[i] = l;
    }
}

__global__ void init_args(const float* bz0, const float* bx0, const float* bx1,
                          const float* bx2, const float* WzL, const float* WxL,
                          float* out)
{
    if (threadIdx.x != 0 || blockIdx.x != 0) return;
    auto set = [] (int p, int nseg, int mode, const float* bias, const float* aux,
                   const bf* sh, const bf* sl, bf* oh, bf* ol, float* ofp) {
        PassArgs& a = g_pass[p];
        a.nseg = nseg; a.mode = mode; a.bias = bias; a.aux = aux;
        a.sh = sh; a.sl = sl; a.oh = oh; a.ol = ol; a.ofp = ofp;
    };
    auto seg = [] (int p, int s, const bf* Ah, const bf* Al, const bf* Bh, const bf* Bl, int K) {
        PassArgs& a = g_pass[p];
        a.Ah[s] = Ah; a.Al[s] = Al; a.Bh[s] = Bh; a.Bl[s] = Bl; a.K[s] = K;
    };
    // forward: z1, z2, z3
    set(0, 1, 0, bz0, 0, 0, 0, g_z_h[0], g_z_l[0], 0);
    seg(0, 0, g_x_h, g_x_l, g_Wz0_h, g_Wz0_l, Dd);
    set(1, 2, 0, bx0, 0, 0, 0, g_z_h[1], g_z_l[1], 0);
    seg(1, 0, g_z_h[0], g_z_l[0], g_Wz_h[0], g_Wz_l[0], Hd);
    seg(1, 1, g_x_h, g_x_l, g_Wx_h[0], g_Wx_l[0], Dd);
    set(2, 2, 0, bx1, 0, 0, 0, g_z_h[2], g_z_l[2], 0);
    seg(2, 0, g_z_h[1], g_z_l[1], g_Wz_h[1], g_Wz_l[1], Hd);
    seg(2, 1, g_x_h, g_x_l, g_Wx_h[1], g_Wx_l[1], Dd);
    // d4 = WzL * sigmoid(pre4)
    set(3, 2, 1, bx2, WzL, 0, 0, g_d4_h, g_d4_l, 0);
    seg(3, 0, g_z_h[2], g_z_l[2], g_Wz_h[2], g_Wz_l[2], Hd);
    seg(3, 1, g_x_h, g_x_l, g_Wx_h[2], g_Wx_l[2], Dd);
    // backward: d3 -> z3 planes, d2 -> z2, d1 -> z1 (in place, s = 1-exp(-z))
    set(4, 1, 2, 0, 0, g_z_h[2], g_z_l[2], g_z_h[2], g_z_l[2], 0);
    seg(4, 0, g_d4_h, g_d4_l, g_WzT_h[2], g_WzT_l[2], Hd);
    set(5, 1, 2, 0, 0, g_z_h[1], g_z_l[1], g_z_h[1], g_z_l[1], 0);
    seg(5, 0, g_z_h[2], g_z_l[2], g_WzT_h[1], g_WzT_l[1], Hd);
    set(6, 1, 2, 0, 0, g_z_h[0], g_z_l[0], g_z_h[0], g_z_l[0], 0);
    seg(6, 0, g_z_h[1], g_z_l[1], g_WzT_h[0], g_WzT_l[0], Hd);
    // grad
    set(7, 4, 3, 0, WxL, 0, 0, 0, 0, out);
    seg(7, 0, g_z_h[0], g_z_l[0], g_GT_h[0], g_GT_l[0], Hd);
    seg(7, 1, g_z_h[1], g_z_l[1], g_GT_h[1], g_GT_l[1], Hd);
    seg(7, 2, g_z_h[2], g_z_l[2], g_GT_h[2], g_GT_l[2], Hd);
    seg(7, 3, g_d4_h, g_d4_l, g_GT_h[3], g_GT_l[3], Hd);
}

// ---------------------------------------------------------------------------
// GEMM pass: CTA 128m x NTn, 256 thr, bf16 3-product mma.sync,
// 3-stage cp.async pipeline, 2 CTAs/SM.
// ---------------------------------------------------------------------------
template <int NT>
__global__ void __launch_bounds__(256, 2) gemm_pass(int pi)
{
    extern __shared__ char smem[];
    const uint32_t smb = smem_u32(smem);
    const PassArgs& a = g_pass[pi];
    const int tid = threadIdx.x, lane = tid & 31, w = tid >> 5;
    const int warpM = w & 3, warpN = w >> 2;
    const int rowbase = blockIdx.y * 128;
    const int nb = blockIdx.x * NT;
    const int NW8 = NT / 16;

    int startc[5]; startc[0] = 0;
    const int nseg = a.nseg;
    for (int s = 0; s < nseg; s++) startc[s + 1] = startc[s] + a.K[s] / 32;
    const int totalc = startc[nseg];

    auto stage = [&](int c, int buf) {
        int s = 0;
        while (c >= startc[s + 1]) s++;
        const int kc = (c - startc[s]) * 32;
        const int Ks = a.K[s];
        const bf *Ah = a.Ah[s], *Al = a.Al[s], *Bh = a.Bh[s], *Bl = a.Bl[s];
        const uint32_t sb = smb + (uint32_t)buf * 32768u;
        #pragma unroll
        for (int it = 0; it < 2; it++) {
            int i = tid + it * 256;
            int r = i >> 2, jb = i & 3;
            uint32_t d = swz(r, jb);
            size_t so = (size_t)(rowbase + r) * Ks + kc + jb * 8;
            cpa16(sb + d, Ah + so);
            cpa16(sb + 8192 + d, Al + so);
        }
        #pragma unroll
        for (int it = 0; it < NT / 64; it++) {
            int i = tid + it * 256;
            int r = i >> 2, jb = i & 3;
            uint32_t d = swz(r, jb);
            size_t so = (size_t)(nb + r) * Ks + kc + jb * 8;
            cpa16(sb + 16384 + d, Bh + so);
            cpa16(sb + 24576 + d, Bl + so);
        }
        CP_COMMIT();
    };

    const int tq = lane >> 3, rq = lane & 7;
    const int mA = warpM * 32 + (tq & 1) * 8 + rq;
    const int kselA = tq >> 1;
    const uint32_t moff = (uint32_t)(mA << 6);
    const int xa = (mA >> 1) & 3;
    const int nB = warpN * (NT / 2) + (tq >> 1) * 8 + rq;
    const int kselB = tq & 1;
    const uint32_t noff = (uint32_t)(nB << 6);
    const int xb = (nB >> 1) & 3;

    float acc[2][8][4];
    #pragma unroll
    for (int i = 0; i < 2; i++)
        #pragma unroll
        for (int j = 0; j < 8; j++)
            #pragma unroll
            for (int cq = 0; cq < 4; cq++) acc[i][j][cq] = 0.0f;

    stage(0, 0);
    if (totalc > 1) stage(1, 1); else CP_COMMIT();

    for (int c = 0; c < totalc; c++) {
        if (c >= totalc - 2) { CP_WAIT0(); } else { CP_WAIT1(); }
        __syncthreads();
        const uint32_t sb = smb + (uint32_t)(c % 3) * 32768u;
        #pragma unroll
        for (int k16 = 0; k16 < 2; k16++) {
            uint32_t ah[2][4], al[2][4];
            #pragma unroll
            for (int mt = 0; mt < 2; mt++) {
                uint32_t ad = sb + moff + (uint32_t)(mt * 1024)
                            + (uint32_t)((((k16 * 2 + kselA) ^ xa)) << 4);
                LDSM4(ah[mt], ad);
                LDSM4(al[mt], ad + 8192);
            }
            #pragma unroll
            for (int ti = 0; ti < NW8 / 2; ti++) {
                uint32_t bh[4], bl[4];
                uint32_t bd = sb + 16384 + noff + (uint32_t)(ti * 1024)
                            + (uint32_t)((((k16 * 2 + kselB) ^ xb)) << 4);
                LDSM4(bh, bd);
                LDSM4(bl, bd + 8192);
                #pragma unroll
                for (int mt = 0; mt < 2; mt++)
                    #pragma unroll
                    for (int jj = 0; jj < 2; jj++) {
                        int j = ti * 2 + jj;
                        MMA16816(acc[mt][j], ah[mt], bh[jj * 2], bh[jj * 2 + 1]);
                        MMA16816(acc[mt][j], al[mt], bh[jj * 2], bh[jj * 2 + 1]);
                        MMA16816(acc[mt][j], ah[mt], bl[jj * 2], bl[jj * 2 + 1]);
                    }
            }
        }
        if (c + 2 < totalc) stage(c + 2, (c + 2) % 3); else CP_COMMIT();
    }

    // ---- epilogue ----
    const int mode = a.mode;
    #pragma unroll
    for (int mt = 0; mt < 2; mt++)
        #pragma unroll
        for (int j = 0; j < NW8; j++) {
            float* q = acc[mt][j];
            const int m0 = rowbase + warpM * 32 + mt * 16 + (lane >> 2);
            const int np = nb + warpN * (NT / 2) + j * 8 + (lane & 3) * 2;
            #pragma unroll
            for (int half = 0; half < 2; half++) {
                const int m = m0 + half * 8;
                float v0 = q[half * 2], v1 = q[half * 2 + 1];
                if (mode == 0) {
                    float p0 = v0 + __ldg(a.bias + np), p1 = v1 + __ldg(a.bias + np + 1);
                    float z0, s0, z1, s1;
                    act(p0, z0, s0); act(p1, z1, s1);
                    st_split(a.oh, a.ol, (size_t)m * Hd + np, z0, z1);
                } else if (mode == 1) {
                    float p0 = v0 + __ldg(a.bias + np), p1 = v1 + __ldg(a.bias + np + 1);
                    float zt, s0, s1;
                    act(p0, zt, s0); act(p1, zt, s1);
                    float d0 = __ldg(a.aux + np) * s0;
                    float d1 = __ldg(a.aux + np + 1) * s1;
                    st_split(a.oh, a.ol, (size_t)m * Hd + np, d0, d1);
                } else if (mode == 2) {
                    size_t o = (size_t)m * Hd + np;
                    uint32_t zh2 = *reinterpret_cast<const uint32_t*>(a.sh + o);
                    uint32_t zl2 = *reinterpret_cast<const uint32_t*>(a.sl + o);
                    __nv_bfloat162 zhh = *reinterpret_cast<__nv_bfloat162*>(&zh2);
                    __nv_bfloat162 zll = *reinterpret_cast<__nv_bfloat162*>(&zl2);
                    float z0 = __bfloat162float(zhh.x) + __bfloat162float(zll.x);
                    float z1 = __bfloat162float(zhh.y) + __bfloat162float(zll.y);
                    float s0 = -expm1f(-z0);     // sigmoid(p) = 1 - exp(-softplus(p))
                    float s1 = -expm1f(-z1);
                    st_split(a.oh, a.ol, o, s0 * v0, s1 * v1);
                } else {
                    float2 r;
                    r.x = v0 + __ldg(a.aux + np);
                    r.y = v1 + __ldg(a.aux + np + 1);
                    *reinterpret_cast<float2*>(a.ofp + (size_t)m * Dd + np) = r;
                }
            }
        }
}

// ---------------------------------------------------------------------------
extern "C" void kernel_launch(void* const* d_in, const int* in_sizes, int n_in,
                              void* d_out, int out_size)
{
    const float* state = (const float*)d_in[0];
    const float* Wz0   = (const float*)d_in[1];
    const float* bz0   = (const float*)d_in[2];
    const float* Wz1   = (const float*)d_in[3];
    const float* Wz2   = (const float*)d_in[4];
    const float* Wz3   = (const float*)d_in[5];
    const float* WzL   = (const float*)d_in[6];
    const float* Wx0   = (const float*)d_in[7];
    const float* bx0   = (const float*)d_in[8];
    const float* Wx1   = (const float*)d_in[9];
    const float* bx1   = (const float*)d_in[10];
    const float* Wx2   = (const float*)d_in[11];
    const float* bx2   = (const float*)d_in[12];
    const float* WxL   = (const float*)d_in[13];
    float* out = (float*)d_out;

    const int smem_bytes = 3 * 32768;   // 96 KB; 2 CTAs/SM = 192 KB
    cudaFuncSetAttribute(gemm_pass<128>, cudaFuncAttributeMaxDynamicSharedMemorySize, smem_bytes);
    cudaFuncSetAttribute(gemm_pass<64>,  cudaFuncAttributeMaxDynamicSharedMemorySize, smem_bytes);

    prep_w<<<512, 256>>>(Wz0, Wz1, Wz2, Wz3, Wx0, Wx1, Wx2);
    prep_x<<<512, 256>>>(state);
    init_args<<<1, 32>>>(bz0, bx0, bx1, bx2, WzL, WxL, out);

    dim3 g128(Hd / 128, Bsz / 128);   // (4, 512)
    dim3 g64(1, Bsz / 128);           // (1, 512)
    for (int p = 0; p < 7; p++)
        gemm_pass<128><<<g128, 256, smem_bytes>>>(p);
    gemm_pass<64><<<g64, 256, smem_bytes>>>(7);
}